// round 13
// baseline (speedup 1.0000x reference)
#include <cuda_runtime.h>
#include <cuda_fp16.h>
#include <math.h>
#include <stdint.h>

#define BATCH 16
#define CIN   128
#define LIN   8192
#define LOUT  16384
#define COUT  128
#define NMT   64                  // original-m per CTA tile (-> 128 outputs)
#define NT    (LIN / NMT)         // 128
#define NCHUNK 12                 // 12 chunks of K=32 (j-space)
#define PA    40                  // A smem pitch (halves): 80B rows
#define PP    72                  // P smem pitch (halves): 144B rows
#define PSB   68                  // S staging pitch (halves)
#define NTH   256

// ---------------- scratch ----------------
__device__ __half g_W[3][COUT * 384];              // w0/w1/w2 fp16 [co][j]
__device__ __half g_mid[(size_t)BATCH * COUT * LOUT];
__device__ float  g_psum  [BATCH * NT * COUT];
__device__ float  g_psumsq[BATCH * NT * COUT];

// ---------------- smem byte offsets ----------------
#define OFF_P   0                  // 384 x 72 x 2 = 55,296 (S staging overlays)
#define OFF_SB  0                  // 3 x 128 x 68 x 2 = 52,224
#define SB_T    (COUT * PSB * 2)   // 17,408 per tap
#define OFF_A   55296              // 3 x 128 x 40 x 2 = 30,720 (single buffer)
#define A_TAP   10240
#define OFF_PL  86016              // 384 fp32
#define OFF_PR  87552              // 384 fp32
#define OFF_CL  89088              // 128 fp32
#define OFF_CR  89600              // 128 fp32
#define SM_TOTAL 90112

// ---------------- PTX helpers (family-portable) ----------------
__device__ __forceinline__ uint32_t smem_u32(const void* p) {
    uint32_t a;
    asm("{ .reg .u64 t; cvta.to.shared.u64 t, %1; cvt.u32.u64 %0, t; }" : "=r"(a) : "l"(p));
    return a;
}
#define CP_ASYNC_CA16(dst, src) \
    asm volatile("cp.async.ca.shared.global [%0], [%1], 16;" :: "r"(dst), "l"(src) : "memory")
#define CP_COMMIT() asm volatile("cp.async.commit_group;" ::: "memory")
#define CP_WAIT(n)  asm volatile("cp.async.wait_group %0;" :: "n"(n) : "memory")

__device__ __forceinline__ void ldsm_x4(uint32_t* r, uint32_t addr) {
    asm volatile("ldmatrix.sync.aligned.m8n8.x4.shared.b16 {%0,%1,%2,%3}, [%4];"
        : "=r"(r[0]), "=r"(r[1]), "=r"(r[2]), "=r"(r[3]) : "r"(addr));
}
__device__ __forceinline__ void ldsm_x4t(uint32_t* r, uint32_t addr) {
    asm volatile("ldmatrix.sync.aligned.m8n8.x4.trans.shared.b16 {%0,%1,%2,%3}, [%4];"
        : "=r"(r[0]), "=r"(r[1]), "=r"(r[2]), "=r"(r[3]) : "r"(addr));
}
__device__ __forceinline__ void mma16816(float* d, const uint32_t* a, uint32_t b0, uint32_t b1) {
    asm volatile("mma.sync.aligned.m16n8k16.row.col.f32.f16.f16.f32 "
        "{%0,%1,%2,%3}, {%4,%5,%6,%7}, {%8,%9}, {%0,%1,%2,%3};"
        : "+f"(d[0]), "+f"(d[1]), "+f"(d[2]), "+f"(d[3])
        : "r"(a[0]), "r"(a[1]), "r"(a[2]), "r"(a[3]), "r"(b0), "r"(b1));
}
__device__ __forceinline__ uint32_t pk(float a, float b) {
    __half2 h = __floats2half2_rn(a, b);
    return *(uint32_t*)&h;
}

// ---------------------------------------------------------------------------
// Kernel 1: W -> three fp16 images g_W[t][co][j]
// ---------------------------------------------------------------------------
__global__ void prep_weights(const float* __restrict__ W) {
    int idx = blockIdx.x * blockDim.x + threadIdx.x;
    if (idx >= COUT * 384) return;
    const float* wp = W + (size_t)idx * 3;
    g_W[0][idx] = __float2half_rn(wp[0]);
    g_W[1][idx] = __float2half_rn(wp[1]);
    g_W[2][idx] = __float2half_rn(wp[2]);
}

__global__ void noop() {}

// ---------------------------------------------------------------------------
// Kernel 2: shared-B 3-GEMM conv, 2 CTAs/SM. Grid (NT, BATCH), 256 threads.
//   S_t[co][m] = sum_j W_t[co][j] * p[j][m]   (K=384, P shared by all taps)
//   even[2m] = S0[m-1]+S1[m]+S2[m],  odd[2m+1] = S0[m]+S1[m]+S2[m+1]
// ---------------------------------------------------------------------------
__global__ __launch_bounds__(NTH, 2)
void conv_kernel(const float* __restrict__ x,
                 const float* __restrict__ bias) {
    extern __shared__ char smem[];
    const uint32_t sb = smem_u32(smem);
    const int b    = blockIdx.y;
    const int tile = blockIdx.x;
    const int m0   = tile * NMT;
    const int tid  = threadIdx.x;
    const int lane = tid & 31;
    const int w    = tid >> 5;
    const int cs    = w >> 1;            // co strip (0..3)
    const int mb    = w & 1;             // m block (0..1)
    const int co0   = cs * 32;
    const int mbase = mb * 32;

    const float* xb = x + (size_t)b * CIN * LIN;

    // ---- prologue: issue A[0] cp.async (L1-cached: 2 CTAs/SM share) ----
    #pragma unroll
    for (int t = 0; t < 6; t++) {
        int idx = tid + t * NTH;         // 0..1535
        int tap = idx >> 9, r = idx & 511;
        int co = r >> 2, g = r & 3;
        uint32_t dst = sb + OFF_A + (uint32_t)(tap * A_TAP + co * 80 + g * 16);
        CP_ASYNC_CA16(dst, g_W[tap] + co * 384 + g * 8);
    }
    CP_COMMIT();

    // ---- build P (384 j-rows x 64 m) directly from gmem + halo arrays ----
    #pragma unroll
    for (int t = 0; t < 4; t++) {
        int idx = tid + t * NTH;         // 0..1023: (ci, octet of 8 m)
        int ci = idx >> 3, oct = idx & 7;
        const float* xr = xb + (size_t)ci * LIN + m0 + oct * 8;
        float4 F0 = *(const float4*)(xr);
        float4 F1 = *(const float4*)(xr + 4);
        float v[8] = {F0.x, F0.y, F0.z, F0.w, F1.x, F1.y, F1.z, F1.w};
        float v2[8], v3[8];
        #pragma unroll
        for (int u = 0; u < 8; u++) { v2[u] = v[u] * v[u]; v3[u] = v2[u] * v[u]; }
        uint32_t base = sb + OFF_P + (uint32_t)(ci * (PP * 2) + oct * 16);
        asm volatile("st.shared.v4.b32 [%0], {%1,%2,%3,%4};" :: "r"(base),
            "r"(pk(v[0], v[1])), "r"(pk(v[2], v[3])), "r"(pk(v[4], v[5])), "r"(pk(v[6], v[7])));
        asm volatile("st.shared.v4.b32 [%0], {%1,%2,%3,%4};" :: "r"(base + 128 * (PP * 2)),
            "r"(pk(v2[0], v2[1])), "r"(pk(v2[2], v2[3])), "r"(pk(v2[4], v2[5])), "r"(pk(v2[6], v2[7])));
        asm volatile("st.shared.v4.b32 [%0], {%1,%2,%3,%4};" :: "r"(base + 256 * (PP * 2)),
            "r"(pk(v3[0], v3[1])), "r"(pk(v3[2], v3[3])), "r"(pk(v3[4], v3[5])), "r"(pk(v3[6], v3[7])));
    }
    {
        float* pL = (float*)(smem + OFF_PL);
        float* pR = (float*)(smem + OFF_PR);
        float* sC = (float*)(smem + OFF_CL);
        #pragma unroll
        for (int t = 0; t < 2; t++) {
            int i = tid + t * NTH;       // 0..511
            if (i < 384) {
                int q = i >> 7, ci = i & 127;
                int posL = m0 - 1, posR = m0 + NMT;
                float xl = (posL >= 0)  ? xb[(size_t)ci * LIN + posL] : 0.f;
                float xr = (posR < LIN) ? xb[(size_t)ci * LIN + posR] : 0.f;
                if (q == 1) { xl *= xl; xr *= xr; }
                else if (q == 2) { xl = xl * xl * xl; xr = xr * xr * xr; }
                pL[i] = xl;
                pR[i] = xr;
            }
        }
        sC[tid] = 0.f;                   // CL[128] + CR[128]
    }

    float acc[3][2][4][4];               // [tap][mt][nt][reg] = 96 regs
    #pragma unroll
    for (int t = 0; t < 3; t++)
        #pragma unroll
        for (int mt = 0; mt < 2; mt++)
            #pragma unroll
            for (int nt = 0; nt < 4; nt++)
                #pragma unroll
                for (int r = 0; r < 4; r++) acc[t][mt][nt][r] = 0.f;

    const uint32_t aRow = lane & 15, aColq = lane >> 4;
    const uint32_t a_off = (uint32_t)(((co0 + aRow) * PA + aColq * 8) * 2);
    const uint32_t b_off = (uint32_t)(aRow * (PP * 2) + (mbase + aColq * 8) * 2);

    for (int c = 0; c < NCHUNK; c++) {
        CP_WAIT(0);
        __syncthreads();                 // A[c] visible (and P on c==0)

        const uint32_t aB = sb + OFF_A + a_off;
        const uint32_t bB = sb + OFF_P + c * 32 * (PP * 2) + b_off;

        #pragma unroll
        for (int ks = 0; ks < 2; ks++) {
            uint32_t bf[2][4];
            ldsm_x4t(bf[0], bB + ks * 16 * (PP * 2));
            ldsm_x4t(bf[1], bB + ks * 16 * (PP * 2) + 32);   // m +16
            #pragma unroll
            for (int t = 0; t < 3; t++) {
                uint32_t af[2][4];
                ldsm_x4(af[0], aB + t * A_TAP + ks * 32);
                ldsm_x4(af[1], aB + t * A_TAP + ks * 32 + 16 * 80);
                #pragma unroll
                for (int mt = 0; mt < 2; mt++)
                    #pragma unroll
                    for (int nt = 0; nt < 4; nt++) {
                        int nb = nt >> 1, pr = (nt & 1) * 2;
                        mma16816(acc[t][mt][nt], af[mt], bf[nb][pr], bf[nb][pr + 1]);
                    }
            }
        }
        // boundary columns (tap0 * pL, tap2 * pR)
        if (tid < 128) {
            const __half* arow = (const __half*)(smem + OFF_A) + tid * PA;
            const float* pl = (const float*)(smem + OFF_PL) + c * 32;
            float* sCL = (float*)(smem + OFF_CL);
            float sum = sCL[tid];
            #pragma unroll
            for (int jl = 0; jl < 32; jl++) sum += __half2float(arow[jl]) * pl[jl];
            sCL[tid] = sum;
        } else {
            int co = tid - 128;
            const __half* arow = (const __half*)(smem + OFF_A + 2 * A_TAP) + co * PA;
            const float* pr = (const float*)(smem + OFF_PR) + c * 32;
            float* sCR = (float*)(smem + OFF_CR);
            float sum = sCR[co];
            #pragma unroll
            for (int jl = 0; jl < 32; jl++) sum += __half2float(arow[jl]) * pr[jl];
            sCR[co] = sum;
        }
        __syncthreads();                 // all reads of A[c] done
        if (c + 1 < NCHUNK) {            // refill single A buffer
            #pragma unroll
            for (int t = 0; t < 6; t++) {
                int idx = tid + t * NTH;
                int tap = idx >> 9, r = idx & 511;
                int co = r >> 2, g = r & 3;
                uint32_t dst = sb + OFF_A + (uint32_t)(tap * A_TAP + co * 80 + g * 16);
                CP_ASYNC_CA16(dst, g_W[tap] + co * 384 + (c + 1) * 32 + g * 8);
            }
            CP_COMMIT();
        }
    }

    // ---- dump S0/S1/S2 to SMEM (overlays P, now dead) ----
    #pragma unroll
    for (int t = 0; t < 3; t++)
        #pragma unroll
        for (int mt = 0; mt < 2; mt++)
            #pragma unroll
            for (int nt = 0; nt < 4; nt++) {
                int co = co0 + mt * 16 + (lane >> 2);
                int m  = mbase + nt * 8 + (lane & 3) * 2;
                uint32_t off = (uint32_t)(OFF_SB + t * SB_T + (co * PSB + m) * 2);
                *(uint32_t*)(smem + off)                 = pk(acc[t][mt][nt][0], acc[t][mt][nt][1]);
                *(uint32_t*)(smem + off + 8 * (PSB * 2)) = pk(acc[t][mt][nt][2], acc[t][mt][nt][3]);
            }
    __syncthreads();

    // ---- combine: even/odd, stats, write g_mid ----
    {
        const __half* S0 = (const __half*)(smem + OFF_SB);
        const __half* S1 = S0 + SB_T / 2;
        const __half* S2 = S1 + SB_T / 2;
        const float* cl = (const float*)(smem + OFF_CL);
        const float* cr = (const float*)(smem + OFF_CR);
        const int co = tid >> 1, h = tid & 1;
        const float bv = __ldg(&bias[co]);
        const __half* s0 = S0 + co * PSB;
        const __half* s1 = S1 + co * PSB;
        const __half* s2 = S2 + co * PSB;
        float s = 0.f, ss = 0.f;
        #pragma unroll
        for (int i = 0; i < 4; i++) {
            int i0 = (2 * i + h) * 8;         // octet start m (0..56)
            float s0prev = (i0 == 0) ? cl[co] : __half2float(s0[i0 - 1]);
            float s2cur  = __half2float(s2[i0]);
            uint32_t outw[8];
            #pragma unroll
            for (int u = 0; u < 8; u++) {
                int m = i0 + u;
                float s0c = __half2float(s0[m]);
                float s1c = __half2float(s1[m]);
                float s2n = (m == NMT - 1) ? cr[co] : __half2float(s2[m + 1]);
                float e = s0prev + s1c + s2cur + bv;
                float o = s0c + s1c + s2n + bv;
                outw[u] = pk(e, o);
                s  += e + o;
                ss += e * e + o * o;
                s0prev = s0c;
                s2cur  = s2n;
            }
            uint4* dst = (uint4*)(g_mid + (size_t)(b * COUT + co) * LOUT + 2 * m0 + i0 * 2);
            dst[0] = make_uint4(outw[0], outw[1], outw[2], outw[3]);
            dst[1] = make_uint4(outw[4], outw[5], outw[6], outw[7]);
        }
        s  += __shfl_xor_sync(0xffffffffu, s, 1, 2);
        ss += __shfl_xor_sync(0xffffffffu, ss, 1, 2);
        if (h == 0) {
            int pidx = (b * NT + tile) * COUT + co;
            g_psum[pidx]   = s;
            g_psumsq[pidx] = ss;
        }
    }
}

// ---------------------------------------------------------------------------
// Kernel 3: fused stats-reduce + normalize + tanh. One block per (b,co) row.
// ---------------------------------------------------------------------------
__global__ __launch_bounds__(256, 8)
void norm_fused(float* __restrict__ out) {
    __shared__ float sstat[2];
    const int row = blockIdx.x;
    const int tid = threadIdx.x;
    if (tid < 32) {
        int b = row >> 7, co = row & 127;
        float s = 0.f, ss = 0.f;
        #pragma unroll
        for (int h = 0; h < 4; h++) {
            int t = tid + h * 32;
            int p = (b * NT + t) * COUT + co;
            s  += g_psum[p];
            ss += g_psumsq[p];
        }
        #pragma unroll
        for (int off = 16; off > 0; off >>= 1) {
            s  += __shfl_xor_sync(0xffffffffu, s, off);
            ss += __shfl_xor_sync(0xffffffffu, ss, off);
        }
        if (tid == 0) {
            double mean = (double)s / (double)LOUT;
            double var  = (double)ss / (double)LOUT - mean * mean;
            sstat[0] = (float)mean;
            sstat[1] = (float)(1.0 / sqrt(var + 1e-5));
        }
    }
    __syncthreads();
    const float mean = sstat[0], rstd = sstat[1];
    const uint4* m8 = (const uint4*)(g_mid + (size_t)row * LOUT);
    float4* o4 = (float4*)(out + (size_t)row * LOUT);
    #pragma unroll
    for (int i = 0; i < 8; i++) {
        int idx = tid + i * 256;
        uint4 v = m8[idx];
        float2 a0 = __half22float2(*(__half2*)&v.x);
        float2 a1 = __half22float2(*(__half2*)&v.y);
        float2 a2 = __half22float2(*(__half2*)&v.z);
        float2 a3 = __half22float2(*(__half2*)&v.w);
        float4 r0, r1;
        r0.x = tanhf((a0.x - mean) * rstd);
        r0.y = tanhf((a0.y - mean) * rstd);
        r0.z = tanhf((a1.x - mean) * rstd);
        r0.w = tanhf((a1.y - mean) * rstd);
        r1.x = tanhf((a2.x - mean) * rstd);
        r1.y = tanhf((a2.y - mean) * rstd);
        r1.z = tanhf((a3.x - mean) * rstd);
        r1.w = tanhf((a3.y - mean) * rstd);
        o4[idx * 2 + 0] = r0;
        o4[idx * 2 + 1] = r1;
    }
}

// ---------------------------------------------------------------------------
extern "C" void kernel_launch(void* const* d_in, const int* in_sizes, int n_in,
                              void* d_out, int out_size) {
    const float* x    = (const float*)d_in[0];
    const float* W    = (const float*)d_in[1];
    const float* bias = (const float*)d_in[2];
    float* out = (float*)d_out;

    cudaFuncSetAttribute(conv_kernel,
                         cudaFuncAttributeMaxDynamicSharedMemorySize, SM_TOTAL);

    prep_weights<<<(COUT * 384 + 255) / 256, 256>>>(W);
    noop<<<1, 32>>>();
    noop<<<1, 32>>>();                  // keeps ncu capture on conv
    conv_kernel<<<dim3(NT, BATCH), NTH, SM_TOTAL>>>(x, bias);
    norm_fused<<<BATCH * COUT, 256>>>(out);
}

// round 14
// speedup vs baseline: 1.2025x; 1.2025x over previous
#include <cuda_runtime.h>
#include <cuda_fp16.h>
#include <math.h>
#include <stdint.h>

#define BATCH 16
#define CIN   128
#define LIN   8192
#define LOUT  16384
#define COUT  128
#define NMT   128                 // original-m per CTA tile (-> 256 outputs)
#define NT    (LIN / NMT)         // 64
#define NCHUNK 12                 // 12 chunks of K=32 (j-space)
#define PA    40                  // A smem pitch (halves): 80B rows
#define PP    136                 // P smem pitch (halves): 272B rows
#define PSB   132                 // S staging pitch (halves)

// ---------------- scratch ----------------
__device__ __half g_W[3][COUT * 384];              // w0/w1/w2 fp16 [co][j]
__device__ __half g_mid[(size_t)BATCH * COUT * LOUT];
__device__ float  g_psum  [BATCH * NT * COUT];
__device__ float  g_psumsq[BATCH * NT * COUT];
__device__ float  g_e0[BATCH * NT * COUT];         // S0[local m=127] per tile
__device__ float  g_e2[BATCH * NT * COUT];         // S2[local m=0]   per tile

// ---------------- smem byte offsets ----------------
#define OFF_P   0                  // 384 x 136 x 2 = 104,448 (S staging overlays)
#define OFF_SB  0                  // 3 x 128 x 132 x 2 = 101,376
#define SB_T    (COUT * PSB * 2)   // 33,792 per tap
#define OFF_A   104448             // 2 buf x 3 tap x 128 x 40 x 2 = 61,440
#define A_TAP   10240
#define A_BUF   30720
#define SM_TOTAL 165888

// ---------------- PTX helpers (family-portable) ----------------
__device__ __forceinline__ uint32_t smem_u32(const void* p) {
    uint32_t a;
    asm("{ .reg .u64 t; cvta.to.shared.u64 t, %1; cvt.u32.u64 %0, t; }" : "=r"(a) : "l"(p));
    return a;
}
#define CP_ASYNC16(dst, src) \
    asm volatile("cp.async.cg.shared.global [%0], [%1], 16;" :: "r"(dst), "l"(src) : "memory")
#define CP_COMMIT() asm volatile("cp.async.commit_group;" ::: "memory")
#define CP_WAIT(n)  asm volatile("cp.async.wait_group %0;" :: "n"(n) : "memory")

__device__ __forceinline__ void ldsm_x4(uint32_t* r, uint32_t addr) {
    asm volatile("ldmatrix.sync.aligned.m8n8.x4.shared.b16 {%0,%1,%2,%3}, [%4];"
        : "=r"(r[0]), "=r"(r[1]), "=r"(r[2]), "=r"(r[3]) : "r"(addr));
}
__device__ __forceinline__ void ldsm_x4t(uint32_t* r, uint32_t addr) {
    asm volatile("ldmatrix.sync.aligned.m8n8.x4.trans.shared.b16 {%0,%1,%2,%3}, [%4];"
        : "=r"(r[0]), "=r"(r[1]), "=r"(r[2]), "=r"(r[3]) : "r"(addr));
}
__device__ __forceinline__ void mma16816(float* d, const uint32_t* a, uint32_t b0, uint32_t b1) {
    asm volatile("mma.sync.aligned.m16n8k16.row.col.f32.f16.f16.f32 "
        "{%0,%1,%2,%3}, {%4,%5,%6,%7}, {%8,%9}, {%0,%1,%2,%3};"
        : "+f"(d[0]), "+f"(d[1]), "+f"(d[2]), "+f"(d[3])
        : "r"(a[0]), "r"(a[1]), "r"(a[2]), "r"(a[3]), "r"(b0), "r"(b1));
}
__device__ __forceinline__ uint32_t pk(float a, float b) {
    __half2 h = __floats2half2_rn(a, b);
    return *(uint32_t*)&h;
}

// ---------------------------------------------------------------------------
// Kernel 1: W -> three fp16 images g_W[t][co][j]
// ---------------------------------------------------------------------------
__global__ void prep_weights(const float* __restrict__ W) {
    int idx = blockIdx.x * blockDim.x + threadIdx.x;
    if (idx >= COUT * 384) return;
    const float* wp = W + (size_t)idx * 3;
    g_W[0][idx] = __float2half_rn(wp[0]);
    g_W[1][idx] = __float2half_rn(wp[1]);
    g_W[2][idx] = __float2half_rn(wp[2]);
}

__global__ void noop() {}

// ---------------------------------------------------------------------------
// Kernel 2: shared-B 3-GEMM conv. Grid (NT, BATCH), 512 threads = 16 warps.
//   S_t[co][m] = sum_j W_t[co][j] * p[j][m]   (K=384, P shared by all taps)
//   even[2m] = S0[m-1]+S1[m]+S2[m],  odd[2m+1] = S0[m]+S1[m]+S2[m+1]
// Boundary terms (S0[m0-1], S2[m0+128]) are patched by fixup_edges.
// ---------------------------------------------------------------------------
__global__ __launch_bounds__(512, 1)
void conv_kernel(const float* __restrict__ x,
                 const float* __restrict__ bias) {
    extern __shared__ char smem[];
    const uint32_t sb = smem_u32(smem);
    const int b    = blockIdx.y;
    const int tile = blockIdx.x;
    const int m0   = tile * NMT;
    const int tid  = threadIdx.x;
    const int lane = tid & 31;
    const int w    = tid >> 5;
    const int cs    = w >> 2;            // co strip (0..3)
    const int mb    = w & 3;             // m block (0..3)
    const int co0   = cs * 32;
    const int mbase = mb * 32;

    const float* xb = x + (size_t)b * CIN * LIN;

    // ---- prologue: issue A[0] cp.async ----
    #pragma unroll
    for (int t = 0; t < 3; t++) {
        int idx = tid + t * 512;         // 0..1535
        int tap = idx >> 9, r = idx & 511;
        int co = r >> 2, g = r & 3;
        uint32_t dst = sb + OFF_A + (uint32_t)(tap * A_TAP + co * 80 + g * 16);
        CP_ASYNC16(dst, g_W[tap] + co * 384 + g * 8);
    }
    CP_COMMIT();

    // ---- build P (384 j-rows x 128 m) directly from gmem ----
    #pragma unroll
    for (int t = 0; t < 4; t++) {
        int idx = tid + t * 512;         // 0..2047: (ci, octet)
        int ci = idx >> 4, oct = idx & 15;
        const float* xr = xb + (size_t)ci * LIN + m0 + oct * 8;
        float4 F0 = *(const float4*)(xr);
        float4 F1 = *(const float4*)(xr + 4);
        float v[8] = {F0.x, F0.y, F0.z, F0.w, F1.x, F1.y, F1.z, F1.w};
        float v2[8], v3[8];
        #pragma unroll
        for (int u = 0; u < 8; u++) { v2[u] = v[u] * v[u]; v3[u] = v2[u] * v[u]; }
        uint32_t base = sb + OFF_P + (uint32_t)(ci * (PP * 2) + oct * 16);
        asm volatile("st.shared.v4.b32 [%0], {%1,%2,%3,%4};" :: "r"(base),
            "r"(pk(v[0], v[1])), "r"(pk(v[2], v[3])), "r"(pk(v[4], v[5])), "r"(pk(v[6], v[7])));
        asm volatile("st.shared.v4.b32 [%0], {%1,%2,%3,%4};" :: "r"(base + 128 * (PP * 2)),
            "r"(pk(v2[0], v2[1])), "r"(pk(v2[2], v2[3])), "r"(pk(v2[4], v2[5])), "r"(pk(v2[6], v2[7])));
        asm volatile("st.shared.v4.b32 [%0], {%1,%2,%3,%4};" :: "r"(base + 256 * (PP * 2)),
            "r"(pk(v3[0], v3[1])), "r"(pk(v3[2], v3[3])), "r"(pk(v3[4], v3[5])), "r"(pk(v3[6], v3[7])));
    }
    CP_WAIT(0);
    __syncthreads();

    float acc[3][2][4][4];               // [tap][mt][nt][reg] = 96 regs
    #pragma unroll
    for (int t = 0; t < 3; t++)
        #pragma unroll
        for (int mt = 0; mt < 2; mt++)
            #pragma unroll
            for (int nt = 0; nt < 4; nt++)
                #pragma unroll
                for (int r = 0; r < 4; r++) acc[t][mt][nt][r] = 0.f;

    const uint32_t aRow = lane & 15, aColq = lane >> 4;
    const uint32_t a_off = (uint32_t)(((co0 + aRow) * PA + aColq * 8) * 2);
    const uint32_t b_off = (uint32_t)(aRow * (PP * 2) + (mbase + aColq * 8) * 2);

    for (int c = 0; c < NCHUNK; c++) {
        const int buf = c & 1;
        if (c + 1 < NCHUNK) {            // prefetch A[c+1]
            #pragma unroll
            for (int t = 0; t < 3; t++) {
                int idx = tid + t * 512;
                int tap = idx >> 9, r = idx & 511;
                int co = r >> 2, g = r & 3;
                uint32_t dst = sb + OFF_A + (uint32_t)(((c + 1) & 1) * A_BUF
                             + tap * A_TAP + co * 80 + g * 16);
                CP_ASYNC16(dst, g_W[tap] + co * 384 + (c + 1) * 32 + g * 8);
            }
            CP_COMMIT();
        }
        const uint32_t aB = sb + OFF_A + buf * A_BUF + a_off;
        const uint32_t bB = sb + OFF_P + c * 32 * (PP * 2) + b_off;

        #pragma unroll
        for (int ks = 0; ks < 2; ks++) {
            uint32_t bf[2][4];
            ldsm_x4t(bf[0], bB + ks * 16 * (PP * 2));
            ldsm_x4t(bf[1], bB + ks * 16 * (PP * 2) + 32);   // m +16
            #pragma unroll
            for (int t = 0; t < 3; t++) {
                uint32_t af[2][4];
                ldsm_x4(af[0], aB + t * A_TAP + ks * 32);
                ldsm_x4(af[1], aB + t * A_TAP + ks * 32 + 16 * 80);
                #pragma unroll
                for (int mt = 0; mt < 2; mt++)
                    #pragma unroll
                    for (int nt = 0; nt < 4; nt++) {
                        int nb = nt >> 1, pr = (nt & 1) * 2;
                        mma16816(acc[t][mt][nt], af[mt], bf[nb][pr], bf[nb][pr + 1]);
                    }
            }
        }
        CP_WAIT(0);
        __syncthreads();
    }

    // ---- dump S0/S1/S2 to SMEM (overlays P, now dead) ----
    #pragma unroll
    for (int t = 0; t < 3; t++)
        #pragma unroll
        for (int mt = 0; mt < 2; mt++)
            #pragma unroll
            for (int nt = 0; nt < 4; nt++) {
                int co = co0 + mt * 16 + (lane >> 2);
                int m  = mbase + nt * 8 + (lane & 3) * 2;
                uint32_t off = (uint32_t)(OFF_SB + t * SB_T + (co * PSB + m) * 2);
                *(uint32_t*)(smem + off)                 = pk(acc[t][mt][nt][0], acc[t][mt][nt][1]);
                *(uint32_t*)(smem + off + 8 * (PSB * 2)) = pk(acc[t][mt][nt][2], acc[t][mt][nt][3]);
            }
    __syncthreads();

    // ---- combine: even/odd (boundary-partial), stats, edges, write g_mid ----
    {
        const __half* S0 = (const __half*)(smem + OFF_SB);
        const __half* S1 = S0 + SB_T / 2;
        const __half* S2 = S1 + SB_T / 2;
        const int co = tid >> 2, oct0 = tid & 3;
        const float bv = __ldg(&bias[co]);
        const __half* s0 = S0 + co * PSB;
        const __half* s1 = S1 + co * PSB;
        const __half* s2 = S2 + co * PSB;
        float s = 0.f, ss = 0.f;
        #pragma unroll
        for (int i = 0; i < 4; i++) {
            int i0 = (i * 4 + oct0) * 8;      // octet start m
            float s0prev = (i0 == 0) ? 0.f : __half2float(s0[i0 - 1]);
            float s2cur  = __half2float(s2[i0]);
            if (i0 == 0)                       // publish S2[0] for tile-1
                g_e2[(b * NT + tile) * COUT + co] = s2cur;
            uint32_t outw[8];
            #pragma unroll
            for (int u = 0; u < 8; u++) {
                int m = i0 + u;
                float s0c = __half2float(s0[m]);
                float s1c = __half2float(s1[m]);
                float s2n = (m == 127) ? 0.f : __half2float(s2[m + 1]);
                float e = s0prev + s1c + s2cur + bv;
                float o = s0c + s1c + s2n + bv;
                outw[u] = pk(e, o);
                s  += e + o;
                ss += e * e + o * o;
                s0prev = s0c;
                s2cur  = s2n;
            }
            if (i0 == 120)                     // publish S0[127] for tile+1
                g_e0[(b * NT + tile) * COUT + co] = s0prev;
            uint4* dst = (uint4*)(g_mid + (size_t)(b * COUT + co) * LOUT + 2 * m0 + i0 * 2);
            dst[0] = make_uint4(outw[0], outw[1], outw[2], outw[3]);
            dst[1] = make_uint4(outw[4], outw[5], outw[6], outw[7]);
        }
        s  += __shfl_xor_sync(0xffffffffu, s, 1, 4);
        s  += __shfl_xor_sync(0xffffffffu, s, 2, 4);
        ss += __shfl_xor_sync(0xffffffffu, ss, 1, 4);
        ss += __shfl_xor_sync(0xffffffffu, ss, 2, 4);
        if (oct0 == 0) {
            int pidx = (b * NT + tile) * COUT + co;
            g_psum[pidx]   = s;
            g_psumsq[pidx] = ss;
        }
    }
}

// ---------------------------------------------------------------------------
// Kernel 2b: patch the 2 boundary output columns per tile with neighbor-tile
// S-edges; adjust that tile's psum/psumsq. Unique owners -> no atomics.
// ---------------------------------------------------------------------------
__global__ void fixup_edges() {
    const int bt = blockIdx.x;           // b*NT + tile
    const int b = bt >> 6, tile = bt & (NT - 1);
    const int co = threadIdx.x;
    float d0 = (tile > 0)      ? g_e0[(b * NT + tile - 1) * COUT + co] : 0.f;
    float d2 = (tile < NT - 1) ? g_e2[(b * NT + tile + 1) * COUT + co] : 0.f;
    __half* row = g_mid + (size_t)(b * COUT + co) * LOUT + tile * 2 * NMT;
    float v0o = __half2float(row[0]);
    float v0n = v0o + d0;
    row[0] = __float2half_rn(v0n);
    float v2o = __half2float(row[255]);
    float v2n = v2o + d2;
    row[255] = __float2half_rn(v2n);
    int pidx = bt * COUT + co;
    g_psum[pidx]   += d0 + d2;
    g_psumsq[pidx] += (v0n * v0n - v0o * v0o) + (v2n * v2n - v2o * v2o);
}

// ---------------------------------------------------------------------------
// Kernel 3: fused stats-reduce + normalize + tanh. One block per (b,co) row.
// ---------------------------------------------------------------------------
__global__ __launch_bounds__(256, 8)
void norm_fused(float* __restrict__ out) {
    __shared__ float sstat[2];
    const int row = blockIdx.x;
    const int tid = threadIdx.x;
    if (tid < 32) {
        int b = row >> 7, co = row & 127;
        float s = 0.f, ss = 0.f;
        #pragma unroll
        for (int h = 0; h < 2; h++) {
            int t = tid + h * 32;
            int p = (b * NT + t) * COUT + co;
            s  += g_psum[p];
            ss += g_psumsq[p];
        }
        #pragma unroll
        for (int off = 16; off > 0; off >>= 1) {
            s  += __shfl_xor_sync(0xffffffffu, s, off);
            ss += __shfl_xor_sync(0xffffffffu, ss, off);
        }
        if (tid == 0) {
            double mean = (double)s / (double)LOUT;
            double var  = (double)ss / (double)LOUT - mean * mean;
            sstat[0] = (float)mean;
            sstat[1] = (float)(1.0 / sqrt(var + 1e-5));
        }
    }
    __syncthreads();
    const float mean = sstat[0], rstd = sstat[1];
    const uint4* m8 = (const uint4*)(g_mid + (size_t)row * LOUT);
    float4* o4 = (float4*)(out + (size_t)row * LOUT);
    #pragma unroll
    for (int i = 0; i < 8; i++) {
        int idx = tid + i * 256;
        uint4 v = m8[idx];
        float2 a0 = __half22float2(*(__half2*)&v.x);
        float2 a1 = __half22float2(*(__half2*)&v.y);
        float2 a2 = __half22float2(*(__half2*)&v.z);
        float2 a3 = __half22float2(*(__half2*)&v.w);
        float4 r0, r1;
        r0.x = tanhf((a0.x - mean) * rstd);
        r0.y = tanhf((a0.y - mean) * rstd);
        r0.z = tanhf((a1.x - mean) * rstd);
        r0.w = tanhf((a1.y - mean) * rstd);
        r1.x = tanhf((a2.x - mean) * rstd);
        r1.y = tanhf((a2.y - mean) * rstd);
        r1.z = tanhf((a3.x - mean) * rstd);
        r1.w = tanhf((a3.y - mean) * rstd);
        o4[idx * 2 + 0] = r0;
        o4[idx * 2 + 1] = r1;
    }
}

// ---------------------------------------------------------------------------
extern "C" void kernel_launch(void* const* d_in, const int* in_sizes, int n_in,
                              void* d_out, int out_size) {
    const float* x    = (const float*)d_in[0];
    const float* W    = (const float*)d_in[1];
    const float* bias = (const float*)d_in[2];
    float* out = (float*)d_out;

    cudaFuncSetAttribute(conv_kernel,
                         cudaFuncAttributeMaxDynamicSharedMemorySize, SM_TOTAL);

    prep_weights<<<(COUT * 384 + 255) / 256, 256>>>(W);
    noop<<<1, 32>>>();
    noop<<<1, 32>>>();                  // keeps ncu capture on conv (#4)
    conv_kernel<<<dim3(NT, BATCH), 512, SM_TOTAL>>>(x, bias);
    fixup_edges<<<BATCH * NT, COUT>>>();
    norm_fused<<<BATCH * COUT, 256>>>(out);
}

// round 15
// speedup vs baseline: 1.3417x; 1.1158x over previous
#include <cuda_runtime.h>
#include <cuda_fp16.h>
#include <math.h>
#include <stdint.h>

#define BATCH 16
#define CIN   128
#define LIN   8192
#define LOUT  16384
#define COUT  128
#define NMT   128                 // original-m per CTA tile (-> 256 outputs)
#define NT    (LIN / NMT)         // 64
#define NCHUNK 12                 // 12 chunks of K=32 (j-space)
#define PP    136                 // P smem pitch (halves): 272B rows
#define PSB   132                 // S staging pitch (halves)

// ---------------- scratch ----------------
__device__ __half g_W[3][COUT * 384];              // w0/w1/w2 fp16 [co][j]
__device__ __half g_mid[(size_t)BATCH * COUT * LOUT];
__device__ float  g_psum  [BATCH * NT * COUT];
__device__ float  g_psumsq[BATCH * NT * COUT];
__device__ float  g_e0[BATCH * NT * COUT];         // S0[local m=127] per tile
__device__ float  g_e2[BATCH * NT * COUT];         // S2[local m=0]   per tile

// ---------------- smem byte offsets ----------------
#define OFF_P   0                  // 384 x 136 x 2 = 104,448 (S staging overlays)
#define OFF_SB  0                  // 3 x 128 x 132 x 2 = 101,376
#define SB_T    (COUT * PSB * 2)   // 33,792 per tap
#define OFF_A   104448             // 4 grp x 2 buf x 3 tap x 32 x 80B = 61,440
#define A_GRP   15360
#define A_BUF   7680
#define A_TAP   2560
#define SM_TOTAL 165888

// ---------------- PTX helpers (family-portable) ----------------
__device__ __forceinline__ uint32_t smem_u32(const void* p) {
    uint32_t a;
    asm("{ .reg .u64 t; cvta.to.shared.u64 t, %1; cvt.u32.u64 %0, t; }" : "=r"(a) : "l"(p));
    return a;
}
#define CP_ASYNC16(dst, src) \
    asm volatile("cp.async.cg.shared.global [%0], [%1], 16;" :: "r"(dst), "l"(src) : "memory")
#define CP_COMMIT() asm volatile("cp.async.commit_group;" ::: "memory")
#define CP_WAIT(n)  asm volatile("cp.async.wait_group %0;" :: "n"(n) : "memory")
#define BAR_GRP(id) asm volatile("bar.sync %0, %1;" :: "r"(id), "r"(128) : "memory")

__device__ __forceinline__ void ldsm_x4(uint32_t* r, uint32_t addr) {
    asm volatile("ldmatrix.sync.aligned.m8n8.x4.shared.b16 {%0,%1,%2,%3}, [%4];"
        : "=r"(r[0]), "=r"(r[1]), "=r"(r[2]), "=r"(r[3]) : "r"(addr));
}
__device__ __forceinline__ void ldsm_x4t(uint32_t* r, uint32_t addr) {
    asm volatile("ldmatrix.sync.aligned.m8n8.x4.trans.shared.b16 {%0,%1,%2,%3}, [%4];"
        : "=r"(r[0]), "=r"(r[1]), "=r"(r[2]), "=r"(r[3]) : "r"(addr));
}
__device__ __forceinline__ void mma16816(float* d, const uint32_t* a, uint32_t b0, uint32_t b1) {
    asm volatile("mma.sync.aligned.m16n8k16.row.col.f32.f16.f16.f32 "
        "{%0,%1,%2,%3}, {%4,%5,%6,%7}, {%8,%9}, {%0,%1,%2,%3};"
        : "+f"(d[0]), "+f"(d[1]), "+f"(d[2]), "+f"(d[3])
        : "r"(a[0]), "r"(a[1]), "r"(a[2]), "r"(a[3]), "r"(b0), "r"(b1));
}
__device__ __forceinline__ uint32_t pk(float a, float b) {
    __half2 h = __floats2half2_rn(a, b);
    return *(uint32_t*)&h;
}

// ---------------------------------------------------------------------------
// Kernel 1: W -> three fp16 images g_W[t][co][j]
// ---------------------------------------------------------------------------
__global__ void prep_weights(const float* __restrict__ W) {
    int idx = blockIdx.x * blockDim.x + threadIdx.x;
    if (idx >= COUT * 384) return;
    const float* wp = W + (size_t)idx * 3;
    g_W[0][idx] = __float2half_rn(wp[0]);
    g_W[1][idx] = __float2half_rn(wp[1]);
    g_W[2][idx] = __float2half_rn(wp[2]);
}

// ---------------------------------------------------------------------------
// Kernel 2: shared-B 3-GEMM conv, group-scoped A staging.
// Grid (NT, BATCH), 512 threads = 16 warps = 4 co-groups of 4 warps.
//   S_t[co][m] = sum_j W_t[co][j] * p[j][m]   (K=384, P shared by all taps)
//   even[2m] = S0[m-1]+S1[m]+S2[m],  odd[2m+1] = S0[m]+S1[m]+S2[m+1]
// Boundary terms are folded in by norm_fused via g_e0/g_e2.
// ---------------------------------------------------------------------------
__global__ __launch_bounds__(512, 1)
void conv_kernel(const float* __restrict__ x,
                 const float* __restrict__ bias) {
    extern __shared__ char smem[];
    const uint32_t sb = smem_u32(smem);
    const int b    = blockIdx.y;
    const int tile = blockIdx.x;
    const int m0   = tile * NMT;
    const int tid  = threadIdx.x;
    const int lane = tid & 31;
    const int w    = tid >> 5;
    const int g     = w >> 2;            // co group (0..3)
    const int mb    = w & 3;             // m block (0..3)
    const int co0   = g * 32;
    const int mbase = mb * 32;
    const int l     = tid & 127;         // thread within group

    const float* xb = x + (size_t)b * CIN * LIN;

    // ---- prologue: issue group-local A[0] cp.async ----
    {
        const uint32_t dst0 = sb + OFF_A + (uint32_t)(g * A_GRP + (l >> 2) * 80 + (l & 3) * 16);
        const __half* src0 = &g_W[0][((g << 5) + (l >> 2)) * 384 + (l & 3) * 8];
        #pragma unroll
        for (int k = 0; k < 3; k++)
            CP_ASYNC16(dst0 + k * A_TAP, src0 + k * (COUT * 384));
        CP_COMMIT();
    }

    // ---- build P (384 j-rows x 128 m) directly from gmem ----
    #pragma unroll
    for (int t = 0; t < 4; t++) {
        int idx = tid + t * 512;         // 0..2047: (ci, octet)
        int ci = idx >> 4, oct = idx & 15;
        const float* xr = xb + (size_t)ci * LIN + m0 + oct * 8;
        float4 F0 = *(const float4*)(xr);
        float4 F1 = *(const float4*)(xr + 4);
        float v[8] = {F0.x, F0.y, F0.z, F0.w, F1.x, F1.y, F1.z, F1.w};
        float v2[8], v3[8];
        #pragma unroll
        for (int u = 0; u < 8; u++) { v2[u] = v[u] * v[u]; v3[u] = v2[u] * v[u]; }
        uint32_t base = sb + OFF_P + (uint32_t)(ci * (PP * 2) + oct * 16);
        asm volatile("st.shared.v4.b32 [%0], {%1,%2,%3,%4};" :: "r"(base),
            "r"(pk(v[0], v[1])), "r"(pk(v[2], v[3])), "r"(pk(v[4], v[5])), "r"(pk(v[6], v[7])));
        asm volatile("st.shared.v4.b32 [%0], {%1,%2,%3,%4};" :: "r"(base + 128 * (PP * 2)),
            "r"(pk(v2[0], v2[1])), "r"(pk(v2[2], v2[3])), "r"(pk(v2[4], v2[5])), "r"(pk(v2[6], v2[7])));
        asm volatile("st.shared.v4.b32 [%0], {%1,%2,%3,%4};" :: "r"(base + 256 * (PP * 2)),
            "r"(pk(v3[0], v3[1])), "r"(pk(v3[2], v3[3])), "r"(pk(v3[4], v3[5])), "r"(pk(v3[6], v3[7])));
    }
    __syncthreads();                     // P visible to all

    float acc[3][2][4][4];               // [tap][mt][nt][reg] = 96 regs
    #pragma unroll
    for (int t = 0; t < 3; t++)
        #pragma unroll
        for (int mt = 0; mt < 2; mt++)
            #pragma unroll
            for (int nt = 0; nt < 4; nt++)
                #pragma unroll
                for (int r = 0; r < 4; r++) acc[t][mt][nt][r] = 0.f;

    const uint32_t aRow = lane & 15, aColq = lane >> 4;
    const uint32_t a_off = (uint32_t)(aRow * 80 + aColq * 16);
    const uint32_t b_off = (uint32_t)(aRow * (PP * 2) + (mbase + aColq * 8) * 2);
    const uint32_t aGrp  = sb + OFF_A + (uint32_t)(g * A_GRP);

    for (int c = 0; c < NCHUNK; c++) {
        CP_WAIT(0);                      // own A[c] copies done
        BAR_GRP(1 + g);                  // group's A[c] visible; prev reads done
        if (c + 1 < NCHUNK) {            // group-local prefetch A[c+1]
            const uint32_t dst0 = aGrp + (uint32_t)(((c + 1) & 1) * A_BUF
                                + (l >> 2) * 80 + (l & 3) * 16);
            const __half* src0 = &g_W[0][((g << 5) + (l >> 2)) * 384 + (c + 1) * 32 + (l & 3) * 8];
            #pragma unroll
            for (int k = 0; k < 3; k++)
                CP_ASYNC16(dst0 + k * A_TAP, src0 + k * (COUT * 384));
            CP_COMMIT();
        }
        const uint32_t aB = aGrp + (c & 1) * A_BUF + a_off;
        const uint32_t bB = sb + OFF_P + c * 32 * (PP * 2) + b_off;

        #pragma unroll
        for (int ks = 0; ks < 2; ks++) {
            uint32_t bf[2][4];
            ldsm_x4t(bf[0], bB + ks * 16 * (PP * 2));
            ldsm_x4t(bf[1], bB + ks * 16 * (PP * 2) + 32);   // m +16
            #pragma unroll
            for (int t = 0; t < 3; t++) {
                uint32_t af[2][4];
                ldsm_x4(af[0], aB + t * A_TAP + ks * 32);
                ldsm_x4(af[1], aB + t * A_TAP + ks * 32 + 16 * 80);
                #pragma unroll
                for (int mt = 0; mt < 2; mt++)
                    #pragma unroll
                    for (int nt = 0; nt < 4; nt++) {
                        int nb = nt >> 1, pr = (nt & 1) * 2;
                        mma16816(acc[t][mt][nt], af[mt], bf[nb][pr], bf[nb][pr + 1]);
                    }
            }
        }
    }
    __syncthreads();                     // all groups done reading P

    // ---- dump S0/S1/S2 to SMEM (overlays P, now dead) ----
    #pragma unroll
    for (int t = 0; t < 3; t++)
        #pragma unroll
        for (int mt = 0; mt < 2; mt++)
            #pragma unroll
            for (int nt = 0; nt < 4; nt++) {
                int co = co0 + mt * 16 + (lane >> 2);
                int m  = mbase + nt * 8 + (lane & 3) * 2;
                uint32_t off = (uint32_t)(OFF_SB + t * SB_T + (co * PSB + m) * 2);
                *(uint32_t*)(smem + off)                 = pk(acc[t][mt][nt][0], acc[t][mt][nt][1]);
                *(uint32_t*)(smem + off + 8 * (PSB * 2)) = pk(acc[t][mt][nt][2], acc[t][mt][nt][3]);
            }
    __syncthreads();

    // ---- combine: even/odd (boundary-partial), stats, edges, write g_mid ----
    {
        const __half* S0 = (const __half*)(smem + OFF_SB);
        const __half* S1 = S0 + SB_T / 2;
        const __half* S2 = S1 + SB_T / 2;
        const int co = tid >> 2, oct0 = tid & 3;
        const float bv = __ldg(&bias[co]);
        const __half* s0 = S0 + co * PSB;
        const __half* s1 = S1 + co * PSB;
        const __half* s2 = S2 + co * PSB;
        float s = 0.f, ss = 0.f;
        #pragma unroll
        for (int i = 0; i < 4; i++) {
            int i0 = (i * 4 + oct0) * 8;      // octet start m
            float s0prev = (i0 == 0) ? 0.f : __half2float(s0[i0 - 1]);
            float s2cur  = __half2float(s2[i0]);
            if (i0 == 0)                       // publish S2[0] for tile-1
                g_e2[(b * NT + tile) * COUT + co] = s2cur;
            uint32_t outw[8];
            #pragma unroll
            for (int u = 0; u < 8; u++) {
                int m = i0 + u;
                float s0c = __half2float(s0[m]);
                float s1c = __half2float(s1[m]);
                float s2n = (m == 127) ? 0.f : __half2float(s2[m + 1]);
                float e = s0prev + s1c + s2cur + bv;
                float o = s0c + s1c + s2n + bv;
                outw[u] = pk(e, o);
                s  += e + o;
                ss += e * e + o * o;
                s0prev = s0c;
                s2cur  = s2n;
            }
            if (i0 == 120)                     // publish S0[127] for tile+1
                g_e0[(b * NT + tile) * COUT + co] = s0prev;
            uint4* dst = (uint4*)(g_mid + (size_t)(b * COUT + co) * LOUT + 2 * m0 + i0 * 2);
            dst[0] = make_uint4(outw[0], outw[1], outw[2], outw[3]);
            dst[1] = make_uint4(outw[4], outw[5], outw[6], outw[7]);
        }
        s  += __shfl_xor_sync(0xffffffffu, s, 1, 4);
        s  += __shfl_xor_sync(0xffffffffu, s, 2, 4);
        ss += __shfl_xor_sync(0xffffffffu, ss, 1, 4);
        ss += __shfl_xor_sync(0xffffffffu, ss, 2, 4);
        if (oct0 == 0) {
            int pidx = (b * NT + tile) * COUT + co;
            g_psum[pidx]   = s;
            g_psumsq[pidx] = ss;
        }
    }
}

// ---------------------------------------------------------------------------
// Kernel 3: fused edge-fixup + stats-reduce + normalize + tanh.
// One block per (b,co) row. Edge corrections applied in-register.
// ---------------------------------------------------------------------------
__global__ __launch_bounds__(256, 8)
void norm_fused(float* __restrict__ out) {
    __shared__ float sD0[NT], sD2[NT];
    __shared__ float spart[4];
    __shared__ float sstat[2];
    const int row = blockIdx.x;
    const int tid = threadIdx.x;
    const int b = row >> 7, co = row & 127;

    if (tid < NT) {                      // 64 threads = 2 warps, one per tile
        int t = tid;
        float d0 = (t > 0)      ? g_e0[(b * NT + t - 1) * COUT + co] : 0.f;
        float d2 = (t < NT - 1) ? g_e2[(b * NT + t + 1) * COUT + co] : 0.f;
        sD0[t] = d0;
        sD2[t] = d2;
        float v0 = __half2float(g_mid[(size_t)row * LOUT + t * 256]);
        float v2 = __half2float(g_mid[(size_t)row * LOUT + t * 256 + 255]);
        float s  = g_psum  [(b * NT + t) * COUT + co] + d0 + d2;
        float ss = g_psumsq[(b * NT + t) * COUT + co]
                 + 2.f * v0 * d0 + d0 * d0 + 2.f * v2 * d2 + d2 * d2;
        #pragma unroll
        for (int off = 16; off > 0; off >>= 1) {
            s  += __shfl_xor_sync(0xffffffffu, s, off);
            ss += __shfl_xor_sync(0xffffffffu, ss, off);
        }
        if ((tid & 31) == 0) {
            spart[(tid >> 5) * 2 + 0] = s;
            spart[(tid >> 5) * 2 + 1] = ss;
        }
    }
    __syncthreads();
    if (tid == 0) {
        double S  = (double)spart[0] + (double)spart[2];
        double SS = (double)spart[1] + (double)spart[3];
        double mean = S / (double)LOUT;
        double var  = SS / (double)LOUT - mean * mean;
        sstat[0] = (float)mean;
        sstat[1] = (float)(1.0 / sqrt(var + 1e-5));
    }
    __syncthreads();
    const float mean = sstat[0], rstd = sstat[1];
    const uint4* m8 = (const uint4*)(g_mid + (size_t)row * LOUT);
    float4* o4 = (float4*)(out + (size_t)row * LOUT);
    #pragma unroll
    for (int i = 0; i < 8; i++) {
        int idx = tid + i * 256;         // 0..2047 (32 uint4 per tile)
        uint4 v = m8[idx];
        float2 a0 = __half22float2(*(__half2*)&v.x);
        float2 a1 = __half22float2(*(__half2*)&v.y);
        float2 a2 = __half22float2(*(__half2*)&v.z);
        float2 a3 = __half22float2(*(__half2*)&v.w);
        int r = idx & 31;
        if (r == 0)  a0.x += sD0[idx >> 5];   // first output of tile
        if (r == 31) a3.y += sD2[idx >> 5];   // last output of tile
        float4 r0, r1;
        r0.x = tanhf((a0.x - mean) * rstd);
        r0.y = tanhf((a0.y - mean) * rstd);
        r0.z = tanhf((a1.x - mean) * rstd);
        r0.w = tanhf((a1.y - mean) * rstd);
        r1.x = tanhf((a2.x - mean) * rstd);
        r1.y = tanhf((a2.y - mean) * rstd);
        r1.z = tanhf((a3.x - mean) * rstd);
        r1.w = tanhf((a3.y - mean) * rstd);
        o4[idx * 2 + 0] = r0;
        o4[idx * 2 + 1] = r1;
    }
}

// ---------------------------------------------------------------------------
extern "C" void kernel_launch(void* const* d_in, const int* in_sizes, int n_in,
                              void* d_out, int out_size) {
    const float* x    = (const float*)d_in[0];
    const float* W    = (const float*)d_in[1];
    const float* bias = (const float*)d_in[2];
    float* out = (float*)d_out;

    cudaFuncSetAttribute(conv_kernel,
                         cudaFuncAttributeMaxDynamicSharedMemorySize, SM_TOTAL);

    prep_weights<<<(COUT * 384 + 255) / 256, 256>>>(W);
    conv_kernel<<<dim3(NT, BATCH), 512, SM_TOTAL>>>(x, bias);
    norm_fused<<<BATCH * COUT, 256>>>(out);
}

// round 16
// speedup vs baseline: 1.4271x; 1.0636x over previous
#include <cuda_runtime.h>
#include <cuda_fp16.h>
#include <math.h>
#include <stdint.h>

#define BATCH 16
#define CIN   128
#define LIN   8192
#define LOUT  16384
#define COUT  128
#define NMT   128                 // original-m per CTA tile (-> 256 outputs)
#define NT    (LIN / NMT)         // 64
#define NCHUNK 12                 // 12 chunks of K=32 (j-space)
#define PP    136                 // P smem pitch (halves): 272B rows
#define PSB   132                 // S staging pitch (halves)

// ---------------- scratch ----------------
// A operand pre-packed in per-lane mma-fragment order:
// record = (g, c, rec=(t*4+ks*2+mt)) -> 32 lanes x uint4 (512 B)
__device__ uint4  g_Wfrag[4 * NCHUNK * 12 * 32];
__device__ __half g_mid[(size_t)BATCH * COUT * LOUT];
__device__ float  g_psum  [BATCH * NT * COUT];
__device__ float  g_psumsq[BATCH * NT * COUT];
__device__ float  g_e0[BATCH * NT * COUT];         // S0[local m=127] per tile
__device__ float  g_e2[BATCH * NT * COUT];         // S2[local m=0]   per tile

// ---------------- smem byte offsets ----------------
#define OFF_P   0                  // 384 x 136 x 2 = 104,448 (S staging overlays)
#define OFF_SB  0                  // 3 x 128 x 132 x 2 = 101,376
#define SB_T    (COUT * PSB * 2)   // 33,792 per tap
#define SM_TOTAL 104448

// ---------------- PTX helpers (family-portable) ----------------
__device__ __forceinline__ uint32_t smem_u32(const void* p) {
    uint32_t a;
    asm("{ .reg .u64 t; cvta.to.shared.u64 t, %1; cvt.u32.u64 %0, t; }" : "=r"(a) : "l"(p));
    return a;
}
__device__ __forceinline__ void ldsm_x4t(uint32_t* r, uint32_t addr) {
    asm volatile("ldmatrix.sync.aligned.m8n8.x4.trans.shared.b16 {%0,%1,%2,%3}, [%4];"
        : "=r"(r[0]), "=r"(r[1]), "=r"(r[2]), "=r"(r[3]) : "r"(addr));
}
__device__ __forceinline__ void mma16816(float* d, const uint32_t* a, uint32_t b0, uint32_t b1) {
    asm volatile("mma.sync.aligned.m16n8k16.row.col.f32.f16.f16.f32 "
        "{%0,%1,%2,%3}, {%4,%5,%6,%7}, {%8,%9}, {%0,%1,%2,%3};"
        : "+f"(d[0]), "+f"(d[1]), "+f"(d[2]), "+f"(d[3])
        : "r"(a[0]), "r"(a[1]), "r"(a[2]), "r"(a[3]), "r"(b0), "r"(b1));
}
__device__ __forceinline__ uint32_t pk(float a, float b) {
    __half2 h = __floats2half2_rn(a, b);
    return *(uint32_t*)&h;
}

// ---------------------------------------------------------------------------
// Kernel 1: W -> g_Wfrag (per-lane mma A-fragment layout).
// Fragment reg mapping (m16k16 row-major A, matches ldsm.x4 convention):
//   reg0 = A[r0][jb], A[r0][jb+1]     reg1 = A[r0+8][jb..jb+1]
//   reg2 = A[r0][jb+8..9]             reg3 = A[r0+8][jb+8..9]
// with r0 = g*32 + mt*16 + (lane>>2), jb = c*32 + ks*16 + (lane&3)*2.
// w_t[co][j] = W[(co*384 + j)*3 + t]
// ---------------------------------------------------------------------------
__global__ void prep_weights(const float* __restrict__ W) {
    int idx = blockIdx.x * blockDim.x + threadIdx.x;
    if (idx >= 4 * NCHUNK * 12 * 32) return;
    int lane = idx & 31;
    int rec  = (idx >> 5) % 12;
    int c    = ((idx >> 5) / 12) % NCHUNK;
    int g    = (idx >> 5) / (12 * NCHUNK);
    int t  = rec >> 2, ks = (rec >> 1) & 1, mt = rec & 1;
    int r0 = g * 32 + mt * 16 + (lane >> 2);
    int jb = c * 32 + ks * 16 + (lane & 3) * 2;
    #define WV(r, j) W[((size_t)(r) * 384 + (j)) * 3 + t]
    uint4 v;
    v.x = pk(WV(r0,     jb),     WV(r0,     jb + 1));
    v.y = pk(WV(r0 + 8, jb),     WV(r0 + 8, jb + 1));
    v.z = pk(WV(r0,     jb + 8), WV(r0,     jb + 9));
    v.w = pk(WV(r0 + 8, jb + 8), WV(r0 + 8, jb + 9));
    #undef WV
    g_Wfrag[idx] = v;
}

// ---------------------------------------------------------------------------
// Kernel 2: shared-B 3-GEMM conv, BARRIER-FREE mainloop (A from GMEM frags).
// Grid (NT, BATCH), 512 threads = 16 warps = 4 co-groups x 4 m-blocks.
//   S_t[co][m] = sum_j W_t[co][j] * p[j][m]
//   even[2m] = S0[m-1]+S1[m]+S2[m],  odd[2m+1] = S0[m]+S1[m]+S2[m+1]
// Boundary terms folded in by norm_fused via g_e0/g_e2.
// ---------------------------------------------------------------------------
__global__ __launch_bounds__(512, 1)
void conv_kernel(const float* __restrict__ x,
                 const float* __restrict__ bias) {
    extern __shared__ char smem[];
    const uint32_t sb = smem_u32(smem);
    const int b    = blockIdx.y;
    const int tile = blockIdx.x;
    const int m0   = tile * NMT;
    const int tid  = threadIdx.x;
    const int lane = tid & 31;
    const int w    = tid >> 5;
    const int g     = w >> 2;            // co group (0..3)
    const int mb    = w & 3;             // m block (0..3)
    const int co0   = g * 32;
    const int mbase = mb * 32;

    const float* xb = x + (size_t)b * CIN * LIN;

    // ---- build P (384 j-rows x 128 m) directly from gmem ----
    #pragma unroll
    for (int t = 0; t < 4; t++) {
        int idx = tid + t * 512;         // 0..2047: (ci, octet)
        int ci = idx >> 4, oct = idx & 15;
        const float* xr = xb + (size_t)ci * LIN + m0 + oct * 8;
        float4 F0 = *(const float4*)(xr);
        float4 F1 = *(const float4*)(xr + 4);
        float v[8] = {F0.x, F0.y, F0.z, F0.w, F1.x, F1.y, F1.z, F1.w};
        float v2[8], v3[8];
        #pragma unroll
        for (int u = 0; u < 8; u++) { v2[u] = v[u] * v[u]; v3[u] = v2[u] * v[u]; }
        uint32_t base = sb + OFF_P + (uint32_t)(ci * (PP * 2) + oct * 16);
        asm volatile("st.shared.v4.b32 [%0], {%1,%2,%3,%4};" :: "r"(base),
            "r"(pk(v[0], v[1])), "r"(pk(v[2], v[3])), "r"(pk(v[4], v[5])), "r"(pk(v[6], v[7])));
        asm volatile("st.shared.v4.b32 [%0], {%1,%2,%3,%4};" :: "r"(base + 128 * (PP * 2)),
            "r"(pk(v2[0], v2[1])), "r"(pk(v2[2], v2[3])), "r"(pk(v2[4], v2[5])), "r"(pk(v2[6], v2[7])));
        asm volatile("st.shared.v4.b32 [%0], {%1,%2,%3,%4};" :: "r"(base + 256 * (PP * 2)),
            "r"(pk(v3[0], v3[1])), "r"(pk(v3[2], v3[3])), "r"(pk(v3[4], v3[5])), "r"(pk(v3[6], v3[7])));
    }
    __syncthreads();                     // P visible to all; ONLY mainloop sync

    float acc[3][2][4][4];               // [tap][mt][nt][reg] = 96 regs
    #pragma unroll
    for (int t = 0; t < 3; t++)
        #pragma unroll
        for (int mt = 0; mt < 2; mt++)
            #pragma unroll
            for (int nt = 0; nt < 4; nt++)
                #pragma unroll
                for (int r = 0; r < 4; r++) acc[t][mt][nt][r] = 0.f;

    const uint32_t aRow = lane & 15, aColq = lane >> 4;
    const uint32_t b_off = (uint32_t)(aRow * (PP * 2) + (mbase + aColq * 8) * 2);
    const uint4* Ag = g_Wfrag + ((size_t)g * NCHUNK * 12) * 32 + lane;

    for (int c = 0; c < NCHUNK; c++) {
        const uint32_t bB = sb + OFF_P + c * 32 * (PP * 2) + b_off;
        const uint4* Ac = Ag + (size_t)c * 12 * 32;
        #pragma unroll
        for (int ks = 0; ks < 2; ks++) {
            uint32_t bf[2][4];
            ldsm_x4t(bf[0], bB + ks * 16 * (PP * 2));
            ldsm_x4t(bf[1], bB + ks * 16 * (PP * 2) + 32);   // m +16
            #pragma unroll
            for (int t = 0; t < 3; t++) {
                uint4 a0 = __ldg(Ac + (t * 4 + ks * 2 + 0) * 32);   // mt=0 frag
                uint4 a1 = __ldg(Ac + (t * 4 + ks * 2 + 1) * 32);   // mt=1 frag
                #pragma unroll
                for (int nt = 0; nt < 4; nt++) {
                    int nb = nt >> 1, pr = (nt & 1) * 2;
                    mma16816(acc[t][0][nt], (const uint32_t*)&a0, bf[nb][pr], bf[nb][pr + 1]);
                    mma16816(acc[t][1][nt], (const uint32_t*)&a1, bf[nb][pr], bf[nb][pr + 1]);
                }
            }
        }
    }
    __syncthreads();                     // all warps done reading P

    // ---- dump S0/S1/S2 to SMEM (overlays P, now dead) ----
    #pragma unroll
    for (int t = 0; t < 3; t++)
        #pragma unroll
        for (int mt = 0; mt < 2; mt++)
            #pragma unroll
            for (int nt = 0; nt < 4; nt++) {
                int co = co0 + mt * 16 + (lane >> 2);
                int m  = mbase + nt * 8 + (lane & 3) * 2;
                uint32_t off = (uint32_t)(OFF_SB + t * SB_T + (co * PSB + m) * 2);
                *(uint32_t*)(smem + off)                 = pk(acc[t][mt][nt][0], acc[t][mt][nt][1]);
                *(uint32_t*)(smem + off + 8 * (PSB * 2)) = pk(acc[t][mt][nt][2], acc[t][mt][nt][3]);
            }
    __syncthreads();

    // ---- combine: even/odd (boundary-partial), stats, edges, write g_mid ----
    {
        const __half* S0 = (const __half*)(smem + OFF_SB);
        const __half* S1 = S0 + SB_T / 2;
        const __half* S2 = S1 + SB_T / 2;
        const int co = tid >> 2, oct0 = tid & 3;
        const float bv = __ldg(&bias[co]);
        const __half* s0 = S0 + co * PSB;
        const __half* s1 = S1 + co * PSB;
        const __half* s2 = S2 + co * PSB;
        float s = 0.f, ss = 0.f;
        #pragma unroll
        for (int i = 0; i < 4; i++) {
            int i0 = (i * 4 + oct0) * 8;      // octet start m
            float s0prev = (i0 == 0) ? 0.f : __half2float(s0[i0 - 1]);
            float s2cur  = __half2float(s2[i0]);
            if (i0 == 0)                       // publish S2[0] for tile-1
                g_e2[(b * NT + tile) * COUT + co] = s2cur;
            uint32_t outw[8];
            #pragma unroll
            for (int u = 0; u < 8; u++) {
                int m = i0 + u;
                float s0c = __half2float(s0[m]);
                float s1c = __half2float(s1[m]);
                float s2n = (m == 127) ? 0.f : __half2float(s2[m + 1]);
                float e = s0prev + s1c + s2cur + bv;
                float o = s0c + s1c + s2n + bv;
                outw[u] = pk(e, o);
                s  += e + o;
                ss += e * e + o * o;
                s0prev = s0c;
                s2cur  = s2n;
            }
            if (i0 == 120)                     // publish S0[127] for tile+1
                g_e0[(b * NT + tile) * COUT + co] = s0prev;
            uint4* dst = (uint4*)(g_mid + (size_t)(b * COUT + co) * LOUT + 2 * m0 + i0 * 2);
            dst[0] = make_uint4(outw[0], outw[1], outw[2], outw[3]);
            dst[1] = make_uint4(outw[4], outw[5], outw[6], outw[7]);
        }
        s  += __shfl_xor_sync(0xffffffffu, s, 1, 4);
        s  += __shfl_xor_sync(0xffffffffu, s, 2, 4);
        ss += __shfl_xor_sync(0xffffffffu, ss, 1, 4);
        ss += __shfl_xor_sync(0xffffffffu, ss, 2, 4);
        if (oct0 == 0) {
            int pidx = (b * NT + tile) * COUT + co;
            g_psum[pidx]   = s;
            g_psumsq[pidx] = ss;
        }
    }
}

// ---------------------------------------------------------------------------
// Kernel 3: fused edge-fixup + stats-reduce + normalize + tanh.
// One block per (b,co) row. Edge corrections applied in-register.
// ---------------------------------------------------------------------------
__global__ __launch_bounds__(256, 8)
void norm_fused(float* __restrict__ out) {
    __shared__ float sD0[NT], sD2[NT];
    __shared__ float spart[4];
    __shared__ float sstat[2];
    const int row = blockIdx.x;
    const int tid = threadIdx.x;
    const int b = row >> 7, co = row & 127;

    if (tid < NT) {                      // 64 threads = 2 warps, one per tile
        int t = tid;
        float d0 = (t > 0)      ? g_e0[(b * NT + t - 1) * COUT + co] : 0.f;
        float d2 = (t < NT - 1) ? g_e2[(b * NT + t + 1) * COUT + co] : 0.f;
        sD0[t] = d0;
        sD2[t] = d2;
        float v0 = __half2float(g_mid[(size_t)row * LOUT + t * 256]);
        float v2 = __half2float(g_mid[(size_t)row * LOUT + t * 256 + 255]);
        float s  = g_psum  [(b * NT + t) * COUT + co] + d0 + d2;
        float ss = g_psumsq[(b * NT + t) * COUT + co]
                 + 2.f * v0 * d0 + d0 * d0 + 2.f * v2 * d2 + d2 * d2;
        #pragma unroll
        for (int off = 16; off > 0; off >>= 1) {
            s  += __shfl_xor_sync(0xffffffffu, s, off);
            ss += __shfl_xor_sync(0xffffffffu, ss, off);
        }
        if ((tid & 31) == 0) {
            spart[(tid >> 5) * 2 + 0] = s;
            spart[(tid >> 5) * 2 + 1] = ss;
        }
    }
    __syncthreads();
    if (tid == 0) {
        double S  = (double)spart[0] + (double)spart[2];
        double SS = (double)spart[1] + (double)spart[3];
        double mean = S / (double)LOUT;
        double var  = SS / (double)LOUT - mean * mean;
        sstat[0] = (float)mean;
        sstat[1] = (float)(1.0 / sqrt(var + 1e-5));
    }
    __syncthreads();
    const float mean = sstat[0], rstd = sstat[1];
    const uint4* m8 = (const uint4*)(g_mid + (size_t)row * LOUT);
    float4* o4 = (float4*)(out + (size_t)row * LOUT);
    #pragma unroll
    for (int i = 0; i < 8; i++) {
        int idx = tid + i * 256;         // 0..2047 (32 uint4 per tile)
        uint4 v = m8[idx];
        float2 a0 = __half22float2(*(__half2*)&v.x);
        float2 a1 = __half22float2(*(__half2*)&v.y);
        float2 a2 = __half22float2(*(__half2*)&v.z);
        float2 a3 = __half22float2(*(__half2*)&v.w);
        int r = idx & 31;
        if (r == 0)  a0.x += sD0[idx >> 5];   // first output of tile
        if (r == 31) a3.y += sD2[idx >> 5];   // last output of tile
        float4 r0, r1;
        r0.x = tanhf((a0.x - mean) * rstd);
        r0.y = tanhf((a0.y - mean) * rstd);
        r0.z = tanhf((a1.x - mean) * rstd);
        r0.w = tanhf((a1.y - mean) * rstd);
        r1.x = tanhf((a2.x - mean) * rstd);
        r1.y = tanhf((a2.y - mean) * rstd);
        r1.z = tanhf((a3.x - mean) * rstd);
        r1.w = tanhf((a3.y - mean) * rstd);
        o4[idx * 2 + 0] = r0;
        o4[idx * 2 + 1] = r1;
    }
}

// ---------------------------------------------------------------------------
extern "C" void kernel_launch(void* const* d_in, const int* in_sizes, int n_in,
                              void* d_out, int out_size) {
    const float* x    = (const float*)d_in[0];
    const float* W    = (const float*)d_in[1];
    const float* bias = (const float*)d_in[2];
    float* out = (float*)d_out;

    cudaFuncSetAttribute(conv_kernel,
                         cudaFuncAttributeMaxDynamicSharedMemorySize, SM_TOTAL);

    prep_weights<<<(4 * NCHUNK * 12 * 32 + 255) / 256, 256>>>(W);
    conv_kernel<<<dim3(NT, BATCH), 512, SM_TOTAL>>>(x, bias);
    norm_fused<<<BATCH * COUT, 256>>>(out);
}

// round 17
// speedup vs baseline: 1.4545x; 1.0192x over previous
#include <cuda_runtime.h>
#include <cuda_fp16.h>
#include <math.h>
#include <stdint.h>

#define BATCH 16
#define CIN   128
#define LIN   8192
#define LOUT  16384
#define COUT  128
#define NMT   128                 // original-m per CTA tile (-> 256 outputs)
#define NT    (LIN / NMT)         // 64
#define NCHUNK 12                 // 12 chunks of K=32 (j-space)
#define PP    136                 // P smem pitch (halves): 272B rows
#define PSB   132                 // S staging pitch (halves)

// ---------------- scratch ----------------
// A operand pre-packed in per-lane mma-fragment order:
// record = (g, c, rec=(t*4+ks*2+mt)) -> 32 lanes x uint4 (512 B)
__device__ uint4  g_Wfrag[4 * NCHUNK * 12 * 32];
__device__ __half g_mid[(size_t)BATCH * COUT * LOUT];
__device__ float  g_psum  [BATCH * NT * COUT];
__device__ float  g_psumsq[BATCH * NT * COUT];
__device__ float  g_e0[BATCH * NT * COUT];         // S0[local m=127] per tile
__device__ float  g_e2[BATCH * NT * COUT];         // S2[local m=0]   per tile

// ---------------- smem byte offsets ----------------
#define OFF_P   0                  // 384 x 136 x 2 = 104,448 (S staging overlays)
#define OFF_SB  0                  // 3 x 128 x 132 x 2 = 101,376
#define SB_T    (COUT * PSB * 2)   // 33,792 per tap
#define SM_TOTAL 104448

// ---------------- PTX helpers (family-portable) ----------------
__device__ __forceinline__ uint32_t smem_u32(const void* p) {
    uint32_t a;
    asm("{ .reg .u64 t; cvta.to.shared.u64 t, %1; cvt.u32.u64 %0, t; }" : "=r"(a) : "l"(p));
    return a;
}
__device__ __forceinline__ void ldsm_x4t(uint32_t* r, uint32_t addr) {
    asm volatile("ldmatrix.sync.aligned.m8n8.x4.trans.shared.b16 {%0,%1,%2,%3}, [%4];"
        : "=r"(r[0]), "=r"(r[1]), "=r"(r[2]), "=r"(r[3]) : "r"(addr));
}
__device__ __forceinline__ void mma16816(float* d, const uint32_t* a, uint32_t b0, uint32_t b1) {
    asm volatile("mma.sync.aligned.m16n8k16.row.col.f32.f16.f16.f32 "
        "{%0,%1,%2,%3}, {%4,%5,%6,%7}, {%8,%9}, {%0,%1,%2,%3};"
        : "+f"(d[0]), "+f"(d[1]), "+f"(d[2]), "+f"(d[3])
        : "r"(a[0]), "r"(a[1]), "r"(a[2]), "r"(a[3]), "r"(b0), "r"(b1));
}
__device__ __forceinline__ uint32_t pk(float a, float b) {
    __half2 h = __floats2half2_rn(a, b);
    return *(uint32_t*)&h;
}

// ---------------------------------------------------------------------------
// Kernel 1: W -> g_Wfrag (per-lane mma A-fragment layout).
//   reg0 = A[r0][jb..jb+1]   reg1 = A[r0+8][jb..jb+1]
//   reg2 = A[r0][jb+8..9]    reg3 = A[r0+8][jb+8..9]
// r0 = g*32 + mt*16 + (lane>>2), jb = c*32 + ks*16 + (lane&3)*2.
// ---------------------------------------------------------------------------
__global__ void prep_weights(const float* __restrict__ W) {
    int idx = blockIdx.x * blockDim.x + threadIdx.x;
    if (idx >= 4 * NCHUNK * 12 * 32) return;
    int lane = idx & 31;
    int rec  = (idx >> 5) % 12;
    int c    = ((idx >> 5) / 12) % NCHUNK;
    int g    = (idx >> 5) / (12 * NCHUNK);
    int t  = rec >> 2, ks = (rec >> 1) & 1, mt = rec & 1;
    int r0 = g * 32 + mt * 16 + (lane >> 2);
    int jb = c * 32 + ks * 16 + (lane & 3) * 2;
    #define WV(r, j) W[((size_t)(r) * 384 + (j)) * 3 + t]
    uint4 v;
    v.x = pk(WV(r0,     jb),     WV(r0,     jb + 1));
    v.y = pk(WV(r0 + 8, jb),     WV(r0 + 8, jb + 1));
    v.z = pk(WV(r0,     jb + 8), WV(r0,     jb + 9));
    v.w = pk(WV(r0 + 8, jb + 8), WV(r0 + 8, jb + 9));
    #undef WV
    g_Wfrag[idx] = v;
}

// ---------------------------------------------------------------------------
// Kernel 2: shared-B 3-GEMM conv, barrier-free mainloop, B-frag pipelined.
// Grid (NT, BATCH), 512 threads = 16 warps = 4 co-groups x 4 m-blocks.
// ---------------------------------------------------------------------------
__global__ __launch_bounds__(512, 1)
void conv_kernel(const float* __restrict__ x,
                 const float* __restrict__ bias) {
    extern __shared__ char smem[];
    const uint32_t sb = smem_u32(smem);
    const int b    = blockIdx.y;
    const int tile = blockIdx.x;
    const int m0   = tile * NMT;
    const int tid  = threadIdx.x;
    const int lane = tid & 31;
    const int w    = tid >> 5;
    const int g     = w >> 2;            // co group (0..3)
    const int mb    = w & 3;             // m block (0..3)
    const int co0   = g * 32;
    const int mbase = mb * 32;

    const float* xb = x + (size_t)b * CIN * LIN;

    // ---- build P (384 j-rows x 128 m) directly from gmem ----
    #pragma unroll
    for (int t = 0; t < 4; t++) {
        int idx = tid + t * 512;         // 0..2047: (ci, octet)
        int ci = idx >> 4, oct = idx & 15;
        const float* xr = xb + (size_t)ci * LIN + m0 + oct * 8;
        float4 F0 = *(const float4*)(xr);
        float4 F1 = *(const float4*)(xr + 4);
        float v[8] = {F0.x, F0.y, F0.z, F0.w, F1.x, F1.y, F1.z, F1.w};
        float v2[8], v3[8];
        #pragma unroll
        for (int u = 0; u < 8; u++) { v2[u] = v[u] * v[u]; v3[u] = v2[u] * v[u]; }
        uint32_t base = sb + OFF_P + (uint32_t)(ci * (PP * 2) + oct * 16);
        asm volatile("st.shared.v4.b32 [%0], {%1,%2,%3,%4};" :: "r"(base),
            "r"(pk(v[0], v[1])), "r"(pk(v[2], v[3])), "r"(pk(v[4], v[5])), "r"(pk(v[6], v[7])));
        asm volatile("st.shared.v4.b32 [%0], {%1,%2,%3,%4};" :: "r"(base + 128 * (PP * 2)),
            "r"(pk(v2[0], v2[1])), "r"(pk(v2[2], v2[3])), "r"(pk(v2[4], v2[5])), "r"(pk(v2[6], v2[7])));
        asm volatile("st.shared.v4.b32 [%0], {%1,%2,%3,%4};" :: "r"(base + 256 * (PP * 2)),
            "r"(pk(v3[0], v3[1])), "r"(pk(v3[2], v3[3])), "r"(pk(v3[4], v3[5])), "r"(pk(v3[6], v3[7])));
    }
    __syncthreads();                     // P visible; only mainloop sync

    float acc[3][2][4][4];               // [tap][mt][nt][reg] = 96 regs
    #pragma unroll
    for (int t = 0; t < 3; t++)
        #pragma unroll
        for (int mt = 0; mt < 2; mt++)
            #pragma unroll
            for (int nt = 0; nt < 4; nt++)
                #pragma unroll
                for (int r = 0; r < 4; r++) acc[t][mt][nt][r] = 0.f;

    const uint32_t aRow = lane & 15, aColq = lane >> 4;
    const uint32_t b_off = (uint32_t)(aRow * (PP * 2) + (mbase + aColq * 8) * 2);
    const uint4* Ag = g_Wfrag + ((size_t)g * NCHUNK * 12) * 32 + lane;

    // B fragments double-buffered one k-step ahead
    uint32_t bf[2][2][4];                // [buf][nb][reg]
    {
        const uint32_t bB0 = sb + OFF_P + b_off;
        ldsm_x4t(bf[0][0], bB0);
        ldsm_x4t(bf[0][1], bB0 + 32);
    }
    for (int c = 0; c < NCHUNK; c++) {
        const uint32_t bB = sb + OFF_P + c * 32 * (PP * 2) + b_off;
        const uint4* Ac = Ag + (size_t)c * 12 * 32;
        #pragma unroll
        for (int ks = 0; ks < 2; ks++) {
            const int cur = ks;
            if (ks == 0) {               // prefetch ks=1
                ldsm_x4t(bf[1][0], bB + 16 * (PP * 2));
                ldsm_x4t(bf[1][1], bB + 16 * (PP * 2) + 32);
            } else if (c + 1 < NCHUNK) { // prefetch next chunk ks=0
                const uint32_t bN = bB + 32 * (PP * 2);
                ldsm_x4t(bf[0][0], bN);
                ldsm_x4t(bf[0][1], bN + 32);
            }
            #pragma unroll
            for (int t = 0; t < 3; t++) {
                uint4 a0 = __ldg(Ac + (t * 4 + ks * 2 + 0) * 32);   // mt=0 frag
                uint4 a1 = __ldg(Ac + (t * 4 + ks * 2 + 1) * 32);   // mt=1 frag
                #pragma unroll
                for (int nt = 0; nt < 4; nt++) {
                    int nb = nt >> 1, pr = (nt & 1) * 2;
                    mma16816(acc[t][0][nt], (const uint32_t*)&a0, bf[cur][nb][pr], bf[cur][nb][pr + 1]);
                    mma16816(acc[t][1][nt], (const uint32_t*)&a1, bf[cur][nb][pr], bf[cur][nb][pr + 1]);
                }
            }
        }
    }
    __syncthreads();                     // all warps done reading P

    // ---- dump S0/S1/S2 to SMEM (overlays P, now dead) ----
    #pragma unroll
    for (int t = 0; t < 3; t++)
        #pragma unroll
        for (int mt = 0; mt < 2; mt++)
            #pragma unroll
            for (int nt = 0; nt < 4; nt++) {
                int co = co0 + mt * 16 + (lane >> 2);
                int m  = mbase + nt * 8 + (lane & 3) * 2;
                uint32_t off = (uint32_t)(OFF_SB + t * SB_T + (co * PSB + m) * 2);
                *(uint32_t*)(smem + off)                 = pk(acc[t][mt][nt][0], acc[t][mt][nt][1]);
                *(uint32_t*)(smem + off + 8 * (PSB * 2)) = pk(acc[t][mt][nt][2], acc[t][mt][nt][3]);
            }
    __syncthreads();

    // ---- combine: even/odd (boundary-partial), stats, edges, write g_mid ----
    {
        const __half* S0 = (const __half*)(smem + OFF_SB);
        const __half* S1 = S0 + SB_T / 2;
        const __half* S2 = S1 + SB_T / 2;
        const int co = tid >> 2, oct0 = tid & 3;
        const float bv = __ldg(&bias[co]);
        const __half* s0 = S0 + co * PSB;
        const __half* s1 = S1 + co * PSB;
        const __half* s2 = S2 + co * PSB;
        float s = 0.f, ss = 0.f;
        #pragma unroll
        for (int i = 0; i < 4; i++) {
            int i0 = (i * 4 + oct0) * 8;      // octet start m
            float s0prev = (i0 == 0) ? 0.f : __half2float(s0[i0 - 1]);
            float s2cur  = __half2float(s2[i0]);
            if (i0 == 0)                       // publish S2[0] for tile-1
                g_e2[(b * NT + tile) * COUT + co] = s2cur;
            uint32_t outw[8];
            #pragma unroll
            for (int u = 0; u < 8; u++) {
                int m = i0 + u;
                float s0c = __half2float(s0[m]);
                float s1c = __half2float(s1[m]);
                float s2n = (m == 127) ? 0.f : __half2float(s2[m + 1]);
                float e = s0prev + s1c + s2cur + bv;
                float o = s0c + s1c + s2n + bv;
                outw[u] = pk(e, o);
                s  += e + o;
                ss += e * e + o * o;
                s0prev = s0c;
                s2cur  = s2n;
            }
            if (i0 == 120)                     // publish S0[127] for tile+1
                g_e0[(b * NT + tile) * COUT + co] = s0prev;
            uint4* dst = (uint4*)(g_mid + (size_t)(b * COUT + co) * LOUT + 2 * m0 + i0 * 2);
            dst[0] = make_uint4(outw[0], outw[1], outw[2], outw[3]);
            dst[1] = make_uint4(outw[4], outw[5], outw[6], outw[7]);
        }
        s  += __shfl_xor_sync(0xffffffffu, s, 1, 4);
        s  += __shfl_xor_sync(0xffffffffu, s, 2, 4);
        ss += __shfl_xor_sync(0xffffffffu, ss, 1, 4);
        ss += __shfl_xor_sync(0xffffffffu, ss, 2, 4);
        if (oct0 == 0) {
            int pidx = (b * NT + tile) * COUT + co;
            g_psum[pidx]   = s;
            g_psumsq[pidx] = ss;
        }
    }
}

// ---------------------------------------------------------------------------
// Kernel 3: fused edge-fixup + stats-reduce + normalize + tanh.
// ---------------------------------------------------------------------------
__global__ __launch_bounds__(256, 8)
void norm_fused(float* __restrict__ out) {
    __shared__ float sD0[NT], sD2[NT];
    __shared__ float spart[4];
    __shared__ float sstat[2];
    const int row = blockIdx.x;
    const int tid = threadIdx.x;
    const int b = row >> 7, co = row & 127;

    if (tid < NT) {                      // 64 threads = 2 warps, one per tile
        int t = tid;
        float d0 = (t > 0)      ? g_e0[(b * NT + t - 1) * COUT + co] : 0.f;
        float d2 = (t < NT - 1) ? g_e2[(b * NT + t + 1) * COUT + co] : 0.f;
        sD0[t] = d0;
        sD2[t] = d2;
        float v0 = __half2float(g_mid[(size_t)row * LOUT + t * 256]);
        float v2 = __half2float(g_mid[(size_t)row * LOUT + t * 256 + 255]);
        float s  = g_psum  [(b * NT + t) * COUT + co] + d0 + d2;
        float ss = g_psumsq[(b * NT + t) * COUT + co]
                 + 2.f * v0 * d0 + d0 * d0 + 2.f * v2 * d2 + d2 * d2;
        #pragma unroll
        for (int off = 16; off > 0; off >>= 1) {
            s  += __shfl_xor_sync(0xffffffffu, s, off);
            ss += __shfl_xor_sync(0xffffffffu, ss, off);
        }
        if ((tid & 31) == 0) {
            spart[(tid >> 5) * 2 + 0] = s;
            spart[(tid >> 5) * 2 + 1] = ss;
        }
    }
    __syncthreads();
    if (tid == 0) {
        double S  = (double)spart[0] + (double)spart[2];
        double SS = (double)spart[1] + (double)spart[3];
        double mean = S / (double)LOUT;
        double var  = SS / (double)LOUT - mean * mean;
        sstat[0] = (float)mean;
        sstat[1] = (float)(1.0 / sqrt(var + 1e-5));
    }
    __syncthreads();
    const float mean = sstat[0], rstd = sstat[1];
    const uint4* m8 = (const uint4*)(g_mid + (size_t)row * LOUT);
    float4* o4 = (float4*)(out + (size_t)row * LOUT);
    #pragma unroll
    for (int i = 0; i < 8; i++) {
        int idx = tid + i * 256;         // 0..2047 (32 uint4 per tile)
        uint4 v = m8[idx];
        float2 a0 = __half22float2(*(__half2*)&v.x);
        float2 a1 = __half22float2(*(__half2*)&v.y);
        float2 a2 = __half22float2(*(__half2*)&v.z);
        float2 a3 = __half22float2(*(__half2*)&v.w);
        int r = idx & 31;
        if (r == 0)  a0.x += sD0[idx >> 5];   // first output of tile
        if (r == 31) a3.y += sD2[idx >> 5];   // last output of tile
        float4 r0, r1;
        r0.x = tanhf((a0.x - mean) * rstd);
        r0.y = tanhf((a0.y - mean) * rstd);
        r0.z = tanhf((a1.x - mean) * rstd);
        r0.w = tanhf((a1.y - mean) * rstd);
        r1.x = tanhf((a2.x - mean) * rstd);
        r1.y = tanhf((a2.y - mean) * rstd);
        r1.z = tanhf((a3.x - mean) * rstd);
        r1.w = tanhf((a3.y - mean) * rstd);
        o4[idx * 2 + 0] = r0;
        o4[idx * 2 + 1] = r1;
    }
}

// ---------------------------------------------------------------------------
extern "C" void kernel_launch(void* const* d_in, const int* in_sizes, int n_in,
                              void* d_out, int out_size) {
    const float* x    = (const float*)d_in[0];
    const float* W    = (const float*)d_in[1];
    const float* bias = (const float*)d_in[2];
    float* out = (float*)d_out;

    cudaFuncSetAttribute(conv_kernel,
                         cudaFuncAttributeMaxDynamicSharedMemorySize, SM_TOTAL);

    prep_weights<<<(4 * NCHUNK * 12 * 32 + 255) / 256, 256>>>(W);
    conv_kernel<<<dim3(NT, BATCH), 512, SM_TOTAL>>>(x, bias);
    norm_fused<<<BATCH * COUT, 256>>>(out);
}